// round 8
// baseline (speedup 1.0000x reference)
#include <cuda_runtime.h>

#define NEG_INF  (-1e8f)
#define M_EMPTY  (-1e30f)
#define INVLN2 1.4426950408889634f
#define LN2    0.6931471805599453f

__device__ __forceinline__ float ex2f(float x){ float r; asm("ex2.approx.ftz.f32 %0, %1;" : "=f"(r) : "f"(x)); return r; }
__device__ __forceinline__ float lg2f(float x){ float r; asm("lg2.approx.ftz.f32 %0, %1;" : "=f"(r) : "f"(x)); return r; }

// log2-domain logsumexp (branch-free)
__device__ __forceinline__ float lse2(float a, float b){
    float m = fmaxf(a, b);
    return m + lg2f(1.0f + ex2f(-fabsf(a - b)));
}
__device__ __forceinline__ float lse3(float a, float b, float c){
    float m = fmaxf(fmaxf(a, b), c);
    return m + lg2f(ex2f(a - m) + ex2f(b - m) + ex2f(c - m));
}
// online-softmax fold: (M,Q) <- (M,Q) + (Ma,Qa). Identity: (M_EMPTY, 0).
// Branch-free: FSETP + SELs only.
__device__ __forceinline__ void mqcomb(float& M, float& Q, float Ma, float Qa){
    float f  = ex2f(-fabsf(M - Ma));
    bool  ge = (M >= Ma);
    float q1 = fmaf(Qa, f, Q);
    float q2 = fmaf(Q,  f, Qa);
    Q = ge ? q1 : q2;
    M = fmaxf(M, Ma);
}

// One CTA (128 threads, 4 warps) per batch. Thread t owns grid columns 2t, 2t+1.
// Row:  u0 = th0 + LSE3(Vdiag + A[0,:]),  u1 = th1 + LSE3(Vup + A[1,:])
//       x_j = LSE(c_j, a_j + x_{j-1}),  c_j = th2 + LSE2(u0_{j-1}+A6, u1_{j-1}+A7),
//       a_j = th2 + A8.
// Factor x_j = S_j + log2 Sum_{k<=j} 2^{c_k - S_k}; S = FADD prefix-sum,
// prefix-LSE via (M,Q) online-softmax Kogge-Stone. ALL conditionals on the
// critical path are identity-element selects (no BSSY/BSYNC).
__global__ __launch_bounds__(128, 1)
void forward_decoder_kernel(const float* __restrict__ theta,
                            const float* __restrict__ A,
                            float* __restrict__ out){
    constexpr int N = 256;
    const int t    = threadIdx.x;     // 0..127
    const int lane = t & 31;
    const int wg   = t >> 5;          // warp 0..3
    const int b    = blockIdx.x;

    __shared__ float sU0[128], sU1[128];
    __shared__ float sMA[2][4], sQA[2][4], sSA[2][4];  // per-row-parity buffers

    const float* thb = theta + (size_t)b * 256 * 256 * 3;
    const float* Ab  = A     + (size_t)b * 256 * 256 * 9;

    // prefetch row 0: 3+9 float2 loads (8B aligned)
    float2 p[12];
    {
        const float2* tp = (const float2*)(thb + 6 * (size_t)t);
        const float2* ap = (const float2*)(Ab + 18 * (size_t)t);
        p[0]=__ldg(tp); p[1]=__ldg(tp+1); p[2]=__ldg(tp+2);
        #pragma unroll
        for(int k = 0; k < 9; k++) p[3+k] = __ldg(ap + k);
    }

    float pv0e=NEG_INF, pv1e=NEG_INF, pv2e=NEG_INF;   // prev-row V at col 2t
    float pv0o=NEG_INF, pv1o=NEG_INF, pv2o=NEG_INF;   // prev-row V at col 2t+1
    float dn0 =NEG_INF, dn1 =NEG_INF, dn2 =NEG_INF;   // prev-row V at col 2t-1

    for(int i = 0; i < N; i++){
        const int ib = i & 1;
        float t0e=p[0].x*INVLN2, t1e=p[0].y*INVLN2, t2e=p[1].x*INVLN2;
        float t0o=p[1].y*INVLN2, t1o=p[2].x*INVLN2, t2o=p[2].y*INVLN2;
        float e0=p[3].x*INVLN2,  e1=p[3].y*INVLN2,  e2=p[4].x*INVLN2;
        float e3=p[4].y*INVLN2,  e4=p[5].x*INVLN2,  e5=p[5].y*INVLN2;
        float e6=p[6].x*INVLN2,  e7=p[6].y*INVLN2,  e8=p[7].x*INVLN2;
        float o0=p[7].y*INVLN2,  o1=p[8].x*INVLN2,  o2=p[8].y*INVLN2;
        float o3=p[9].x*INVLN2,  o4=p[9].y*INVLN2,  o5=p[10].x*INVLN2;
        float o6=p[10].y*INVLN2, o7=p[11].x*INVLN2, o8=p[11].y*INVLN2;

        // next row's loads (hide DRAM under this row's compute)
        if(i + 1 < N){
            const float2* tp = (const float2*)(thb + (size_t)(i+1)*768  + 6  * (size_t)t);
            const float2* ap = (const float2*)(Ab  + (size_t)(i+1)*2304 + 18 * (size_t)t);
            p[0]=__ldg(tp); p[1]=__ldg(tp+1); p[2]=__ldg(tp+2);
            #pragma unroll
            for(int k = 0; k < 9; k++) p[3+k] = __ldg(ap + k);
        }

        // diagonal for even column (branchless boundary)
        float bv = (i == 0) ? 0.0f : NEG_INF;
        float d0 = (t == 0) ? bv : dn0;
        float d1 = (t == 0) ? bv : dn1;
        float d2 = (t == 0) ? bv : dn2;

        float u0e  = t0e + lse3(d0  + e0, d1  + e1, d2  + e2);
        float u1e  = t1e + lse3(pv0e + e3, pv1e + e4, pv2e + e5);
        float nu0o = t0o + lse3(pv0e + o0, pv1e + o1, pv2e + o2);
        float nu1o = t1o + lse3(pv0o + o3, pv1o + o4, pv2o + o5);

        // FADD prefix-sum of a over lanes (branchless: +0 identity)
        float a_e = t2e + e8, a_o = t2o + o8;
        float Sin = a_e + a_o;
        #pragma unroll
        for(int dlt = 1; dlt < 32; dlt <<= 1){
            float v = __shfl_up_sync(0xffffffffu, Sin, dlt);
            Sin += (lane >= dlt) ? v : 0.0f;
        }

        sU0[t] = nu0o; sU1[t] = nu1o;
        if(lane == 31) sSA[ib][wg] = Sin;
        __syncthreads();                       // bar A: u exchange + S aggregates

        float num0 = (t != 0) ? sU0[t-1] : NEG_INF;
        float num1 = (t != 0) ? sU1[t-1] : NEG_INF;

        float c_e = t2e + lse2(num0 + e6, num1 + e7);   // col 2t
        float c_o = t2o + lse2(u0e  + o6, u1e  + o7);   // col 2t+1

        // warp-local frame T = c - S_local
        float Sl_o = Sin;
        float Sl_e = Sin - a_o;
        float Te = c_e - Sl_e;
        float To = c_o - Sl_o;

        // thread element 2^Te + 2^To as (M,Q)
        float Mi = fmaxf(Te, To);
        float Qi = 1.0f + ex2f(-fabsf(Te - To));

        // intra-warp inclusive (M,Q) scan — unconditional combine w/ identity mask
        #pragma unroll
        for(int dlt = 1; dlt < 32; dlt <<= 1){
            float Mn = __shfl_up_sync(0xffffffffu, Mi, dlt);
            float Qn = __shfl_up_sync(0xffffffffu, Qi, dlt);
            bool take = (lane >= dlt);
            Mn = take ? Mn : M_EMPTY;
            Qn = take ? Qn : 0.0f;
            mqcomb(Mi, Qi, Mn, Qn);
        }
        // lane-exclusive (branchless)
        float eM = __shfl_up_sync(0xffffffffu, Mi, 1);
        float eQ = __shfl_up_sync(0xffffffffu, Qi, 1);
        eM = (lane == 0) ? M_EMPTY : eM;
        eQ = (lane == 0) ? 0.0f    : eQ;

        if(lane == 31){ sMA[ib][wg] = Mi; sQA[ib][wg] = Qi; }
        __syncthreads();                       // bar B: warp aggregates ready

        // fold aggregates of warps < wg into (Mp,Qp); shift each into the true
        // frame by the running S prefix. Branchless conditional commit.
        float Mp = M_EMPTY, Qp = 0.0f, run = 0.0f;
        #pragma unroll
        for(int v = 0; v < 3; v++){
            float Ma = sMA[ib][v] - run;
            float Qa = sQA[ib][v];
            float f  = ex2f(-fabsf(Mp - Ma));
            bool  ge = (Mp >= Ma);
            float q1 = fmaf(Qa, f, Qp);
            float q2 = fmaf(Qp, f, Qa);
            float Qx = ge ? q1 : q2;
            float Mx = fmaxf(Mp, Ma);
            float rn = run + sSA[ib][v];
            bool tk = (v < wg);
            Mp  = tk ? Mx : Mp;
            Qp  = tk ? Qx : Qp;
            run = tk ? rn : run;
        }
        float Swpre = run;
        float S_o = Swpre + Sl_o;
        float S_e = S_o - a_o;

        // x at col 2t-1 (next row's diag V2)
        float M1 = Mp, Q1 = Qp;
        mqcomb(M1, Q1, eM - Swpre, eQ);
        float dn2n = (S_e - a_e) + M1 + lg2f(Q1);

        // x at even col
        float M2 = M1, Q2 = Q1;
        mqcomb(M2, Q2, Te - Swpre, 1.0f);
        float x_e = S_e + M2 + lg2f(Q2);

        // x at odd col
        float M3 = Mp, Q3 = Qp;
        mqcomb(M3, Q3, Mi - Swpre, Qi);
        float x_o = S_o + M3 + lg2f(Q3);

        pv0e = u0e;  pv1e = u1e;  pv2e = x_e;
        pv0o = nu0o; pv1o = nu1o; pv2o = x_o;
        dn0  = num0; dn1  = num1; dn2  = dn2n;
    }

    // terminal logsumexp at grid cell (N, M) = odd column of t=127
    if(t == 127) out[b] = LN2 * lse3(pv0o, pv1o, pv2o);
}

extern "C" void kernel_launch(void* const* d_in, const int* in_sizes, int n_in,
                              void* d_out, int out_size) {
    const float* theta = (const float*)d_in[0];
    const float* A     = (const float*)d_in[1];
    // d_in[2] = pos: fixed [(-1,-1),(-1,0),(0,-1)] -> (diag, up, left), hard-coded.
    float* out = (float*)d_out;
    int B = out_size;                 // 128 batches, one CTA each
    forward_decoder_kernel<<<B, 128>>>(theta, A, out);
}

// round 11
// speedup vs baseline: 1.0885x; 1.0885x over previous
#include <cuda_runtime.h>
#include <cstdint>

#define NEG_INF  (-1e8f)
#define M_EMPTY  (-1e30f)
#define INVLN2 1.4426950408889634f
#define LN2    0.6931471805599453f

__device__ __forceinline__ float ex2f(float x){ float r; asm("ex2.approx.ftz.f32 %0, %1;" : "=f"(r) : "f"(x)); return r; }
__device__ __forceinline__ float lg2f(float x){ float r; asm("lg2.approx.ftz.f32 %0, %1;" : "=f"(r) : "f"(x)); return r; }

__device__ __forceinline__ float lse2(float a, float b){
    float m = fmaxf(a, b);
    return m + lg2f(1.0f + ex2f(-fabsf(a - b)));
}
__device__ __forceinline__ float lse3(float a, float b, float c){
    float m = fmaxf(fmaxf(a, b), c);
    return m + lg2f(ex2f(a - m) + ex2f(b - m) + ex2f(c - m));
}
// online-softmax fold, identity (M_EMPTY, 0); branch-free
__device__ __forceinline__ void mqcomb(float& M, float& Q, float Ma, float Qa){
    float f  = ex2f(-fabsf(M - Ma));
    bool  ge = (M >= Ma);
    float q1 = fmaf(Qa, f, Q);
    float q2 = fmaf(Q,  f, Qa);
    Q = ge ? q1 : q2;
    M = fmaxf(M, Ma);
}

__device__ __forceinline__ void st_release_s32(uint32_t saddr, int v){
    asm volatile("st.release.cta.shared::cta.u32 [%0], %1;" :: "r"(saddr), "r"(v) : "memory");
}
__device__ __forceinline__ int ld_acquire_s32(uint32_t saddr){
    int v;
    asm volatile("ld.acquire.cta.shared::cta.u32 %0, [%1];" : "=r"(v) : "r"(saddr) : "memory");
    return v;
}
__device__ __forceinline__ uint32_t smem_u32(const void* p){
    return (uint32_t)__cvta_generic_to_shared(p);
}

// One CTA (4 warps) per batch. Warp w owns columns [64w, 64w+64); lane owns
// cols 64w+2*lane (even) and +1 (odd). Prev-row V lives in registers.
// Inter-warp: 3-float edge carry (u0,u1,x at col 64w+63) via smem ring +
// acquire/release flags. Each warp runs rows 0..255 independently; the
// pipeline (warp w on row r while w+1 is on row r-1) forms itself.
// Row math (log2 domain): u0 = th0+LSE3(Vdiag+A[0,:]); u1 = th1+LSE3(Vup+A[1,:])
//   x_j = LSE(c_j, a_j + x_{j-1}); c_j = th2+LSE2(u0_{j-1}+A6, u1_{j-1}+A7); a_j = th2+A8
// Factored: x_j = S_j + lg2( sum_{k<=j} 2^{c_k - S_k} + 2^{x_in} ), S = local FADD prefix.
// Lane-0's c and x_in are folded AFTER the local scan (both only need the payload).
__global__ __launch_bounds__(128, 1)
void forward_decoder_kernel(const float* __restrict__ theta,
                            const float* __restrict__ A,
                            float* __restrict__ out){
    constexpr int N = 256;
    const int lane = threadIdx.x & 31;
    const int w    = threadIdx.x >> 5;          // warp 0..3 = pipeline stage
    const int b    = blockIdx.x;

    __shared__ float4  pay[4][8];               // [producer warp][row&7] = {u0,u1,x,_}
    __shared__ uint32_t flag[4];                // rows published by warp w
    __shared__ uint32_t ack[4];                 // rows consumed by warp w
    if(threadIdx.x < 4){ flag[threadIdx.x] = 0; ack[threadIdx.x] = 0; }
    __syncthreads();                            // once; no barriers in the row loop

    const uint32_t flag_prev = smem_u32(&flag[(w + 3) & 3]);
    const uint32_t flag_own  = smem_u32(&flag[w]);
    const uint32_t ack_own   = smem_u32(&ack[w]);
    const uint32_t ack_next  = smem_u32(&ack[(w + 1) & 3]);

    const int jc = (w << 6) + (lane << 1);      // even column
    const float* thb = theta + (size_t)b * 196608 + (size_t)jc * 3;
    const float* Ab  = A     + (size_t)b * 589824 + (size_t)jc * 9;

    // prefetch row 0 (3 + 9 float2, 8B aligned)
    float2 p[12];
    {
        const float2* tp = (const float2*)thb;
        const float2* ap = (const float2*)Ab;
        p[0]=__ldg(tp); p[1]=__ldg(tp+1); p[2]=__ldg(tp+2);
        #pragma unroll
        for(int k = 0; k < 9; k++) p[3+k] = __ldg(ap + k);
    }

    float pv0e=NEG_INF, pv1e=NEG_INF, pv2e=NEG_INF;  // prev-row V, even col
    float pv0o=NEG_INF, pv1o=NEG_INF, pv2o=NEG_INF;  // prev-row V, odd col
    // prev-row V at col 64w-1 (lane0 diag); warp0 row0 boundary V[0,0]=0
    float pp0 = (w == 0) ? 0.0f : NEG_INF, pp1 = pp0, pp2 = pp0;

    for(int r = 0; r < N; r++){
        // ---- consume prefetched row, issue next row's loads ----
        float t0e=p[0].x*INVLN2, t1e=p[0].y*INVLN2, t2e=p[1].x*INVLN2;
        float t0o=p[1].y*INVLN2, t1o=p[2].x*INVLN2, t2o=p[2].y*INVLN2;
        float e0=p[3].x*INVLN2,  e1=p[3].y*INVLN2,  e2=p[4].x*INVLN2;
        float e3=p[4].y*INVLN2,  e4=p[5].x*INVLN2,  e5=p[5].y*INVLN2;
        float e6=p[6].x*INVLN2,  e7=p[6].y*INVLN2,  e8=p[7].x*INVLN2;
        float o0=p[7].y*INVLN2,  o1=p[8].x*INVLN2,  o2=p[8].y*INVLN2;
        float o3=p[9].x*INVLN2,  o4=p[9].y*INVLN2,  o5=p[10].x*INVLN2;
        float o6=p[10].y*INVLN2, o7=p[11].x*INVLN2, o8=p[11].y*INVLN2;
        if(r + 1 < N){
            const float2* tp = (const float2*)(thb + (size_t)(r+1)*768);
            const float2* ap = (const float2*)(Ab  + (size_t)(r+1)*2304);
            p[0]=__ldg(tp); p[1]=__ldg(tp+1); p[2]=__ldg(tp+2);
            #pragma unroll
            for(int k = 0; k < 9; k++) p[3+k] = __ldg(ap + k);
        }

        // ---- local heads (no external deps) ----
        float d0s = __shfl_up_sync(0xffffffffu, pv0o, 1);
        float d1s = __shfl_up_sync(0xffffffffu, pv1o, 1);
        float d2s = __shfl_up_sync(0xffffffffu, pv2o, 1);
        float d0 = (lane == 0) ? pp0 : d0s;
        float d1 = (lane == 0) ? pp1 : d1s;
        float d2 = (lane == 0) ? pp2 : d2s;

        float u0e  = t0e + lse3(d0   + e0, d1   + e1, d2   + e2);
        float u1e  = t1e + lse3(pv0e + e3, pv1e + e4, pv2e + e5);
        float nu0o = t0o + lse3(pv0e + o0, pv1e + o1, pv2e + o2);
        float nu1o = t1o + lse3(pv0o + o3, pv1o + o4, pv2o + o5);

        float num0 = __shfl_up_sync(0xffffffffu, nu0o, 1);  // lane0 unused
        float num1 = __shfl_up_sync(0xffffffffu, nu1o, 1);

        // FADD prefix-sum of a (warp-local frame)
        float a_e = t2e + e8, a_o = t2o + o8;
        float Sin = a_e + a_o;
        #pragma unroll
        for(int dlt = 1; dlt < 32; dlt <<= 1){
            float v = __shfl_up_sync(0xffffffffu, Sin, dlt);
            Sin += (lane >= dlt) ? v : 0.0f;
        }
        float Sl_o = Sin, Sl_e = Sin - a_o;

        float c_o = t2o + lse2(u0e  + o6, u1e  + o7);
        float c_e = t2e + lse2(num0 + e6, num1 + e7);   // lane0 deferred
        float Te  = (lane == 0) ? M_EMPTY : c_e - Sl_e;
        float To  = c_o - Sl_o;

        float Mi = fmaxf(Te, To);
        float Qi = 1.0f + ex2f(-fabsf(Te - To));
        #pragma unroll
        for(int dlt = 1; dlt < 32; dlt <<= 1){
            float Mn = __shfl_up_sync(0xffffffffu, Mi, dlt);
            float Qn = __shfl_up_sync(0xffffffffu, Qi, dlt);
            bool take = (lane >= dlt);
            Mn = take ? Mn : M_EMPTY;
            Qn = take ? Qn : 0.0f;
            mqcomb(Mi, Qi, Mn, Qn);
        }
        // prefix-through-Te = exclusive ⊕ own even element
        float eM = __shfl_up_sync(0xffffffffu, Mi, 1);
        float eQ = __shfl_up_sync(0xffffffffu, Qi, 1);
        float WeM = (lane == 0) ? M_EMPTY : eM;
        float WeQ = (lane == 0) ? 0.0f    : eQ;
        mqcomb(WeM, WeQ, Te, 1.0f);

        // ---- wait for edge carry from warp w-1 (already posted in steady state) ----
        float u0in = NEG_INF, u1in = NEG_INF, xin = NEG_INF;
        if(w > 0){
            while(ld_acquire_s32(flag_prev) < r + 1){ }
            float4 ps = pay[w-1][r & 7];
            u0in = ps.x; u1in = ps.y; xin = ps.z;
            if(lane == 0) st_release_s32(ack_own, r + 1);
        }

        // deferred lane-0 element + incoming x, folded as one (M,Q) element
        float ce0 = t2e + lse2(u0in + e6, u1in + e7);   // meaningful on lane 0
        float cb  = __shfl_sync(0xffffffffu, ce0 - a_e, 0);
        float zM  = fmaxf(xin, cb);
        float zQ  = 1.0f + ex2f(-fabsf(xin - cb));

        mqcomb(WeM, WeQ, zM, zQ);
        float x_e = Sl_e + WeM + lg2f(WeQ);
        float XoM = Mi, XoQ = Qi;
        mqcomb(XoM, XoQ, zM, zQ);
        float x_o = Sl_o + XoM + lg2f(XoQ);

        // ---- post edge carry to warp w+1 ----
        if(w < 3){
            if(lane == 31){
                while(ld_acquire_s32(ack_next) < r - 7){ }   // ring back-pressure
                pay[w][r & 7] = make_float4(nu0o, nu1o, x_o, 0.0f);
                st_release_s32(flag_own, r + 1);
            }
        }

        // ---- roll state ----
        pv0e = u0e;  pv1e = u1e;  pv2e = x_e;
        pv0o = nu0o; pv1o = nu1o; pv2o = x_o;
        pp0 = u0in; pp1 = u1in; pp2 = xin;   // prev-row V at col 64w-1 (warp0: NEG_INF)
    }

    // terminal: logsumexp over states at grid cell (N, M) = odd col of warp3 lane31
    if(w == 3 && lane == 31) out[b] = LN2 * lse3(pv0o, pv1o, pv2o);
}

extern "C" void kernel_launch(void* const* d_in, const int* in_sizes, int n_in,
                              void* d_out, int out_size) {
    const float* theta = (const float*)d_in[0];
    const float* A     = (const float*)d_in[1];
    // d_in[2] = pos: fixed [(-1,-1),(-1,0),(0,-1)] -> (diag, up, left), hard-coded.
    float* out = (float*)d_out;
    int B = out_size;                 // 128 batches, one CTA each
    forward_decoder_kernel<<<B, 128>>>(theta, A, out);
}

// round 13
// speedup vs baseline: 1.3670x; 1.2559x over previous
#include <cuda_runtime.h>
#include <cstdint>

#define NEG_INF  (-1e8f)
#define M_EMPTY  (-1e30f)
#define INVLN2 1.4426950408889634f
#define LN2    0.6931471805599453f

__device__ __forceinline__ float ex2f(float x){ float r; asm("ex2.approx.ftz.f32 %0, %1;" : "=f"(r) : "f"(x)); return r; }
__device__ __forceinline__ float lg2f(float x){ float r; asm("lg2.approx.ftz.f32 %0, %1;" : "=f"(r) : "f"(x)); return r; }

__device__ __forceinline__ float lse2(float a, float b){
    float m = fmaxf(a, b);
    return m + lg2f(1.0f + ex2f(-fabsf(a - b)));
}
__device__ __forceinline__ float lse3(float a, float b, float c){
    float m = fmaxf(fmaxf(a, b), c);
    return m + lg2f(ex2f(a - m) + ex2f(b - m) + ex2f(c - m));
}
// online-softmax fold, identity (M_EMPTY, 0); branch-free
__device__ __forceinline__ void mqcomb(float& M, float& Q, float Ma, float Qa){
    float f  = ex2f(-fabsf(M - Ma));
    bool  ge = (M >= Ma);
    float q1 = fmaf(Qa, f, Q);
    float q2 = fmaf(Q,  f, Qa);
    Q = ge ? q1 : q2;
    M = fmaxf(M, Ma);
}

__device__ __forceinline__ void st_release_s32(uint32_t saddr, int v){
    asm volatile("st.release.cta.shared::cta.u32 [%0], %1;" :: "r"(saddr), "r"(v) : "memory");
}
__device__ __forceinline__ int ld_acquire_s32(uint32_t saddr){
    int v;
    asm volatile("ld.acquire.cta.shared::cta.u32 %0, [%1];" : "=r"(v) : "r"(saddr) : "memory");
    return v;
}
__device__ __forceinline__ uint32_t smem_u32(const void* p){
    return (uint32_t)__cvta_generic_to_shared(p);
}

// One CTA (4 warps) per batch; warp w = pipeline stage owning cols [64w,64w+64).
// Same math as R11 (log2 domain, S/T factorization, MQ online-softmax scan,
// smem carry ring between warps). NEW: software pipelining across rows.
// Each head u = t + LSE3(V0+a, V1+b, V2+c) is split into
//   u = t + LSE2(P, V2+c),  P = LSE2(V0+a, V1+b)
// where P for row r+1 is computed in row r's TAIL (V0,V1 = u-values, ready
// mid-row) so only a single lse2 per head sits on the cross-row x-chain.
// All INVLN2 scalings folded into FMAs.
__global__ __launch_bounds__(128, 1)
void forward_decoder_kernel(const float* __restrict__ theta,
                            const float* __restrict__ A,
                            float* __restrict__ out){
    constexpr int N = 256;
    const int lane = threadIdx.x & 31;
    const int w    = threadIdx.x >> 5;
    const int b    = blockIdx.x;

    __shared__ float4  pay[4][8];
    __shared__ uint32_t flag[4];
    __shared__ uint32_t ack[4];
    if(threadIdx.x < 4){ flag[threadIdx.x] = 0; ack[threadIdx.x] = 0; }
    __syncthreads();   // only barrier in the kernel

    const uint32_t flag_prev = smem_u32(&flag[(w + 3) & 3]);
    const uint32_t flag_own  = smem_u32(&flag[w]);
    const uint32_t ack_own   = smem_u32(&ack[w]);
    const uint32_t ack_next  = smem_u32(&ack[(w + 1) & 3]);

    const int jc = (w << 6) + (lane << 1);
    const float* thb = theta + (size_t)b * 196608 + (size_t)jc * 3;
    const float* Ab  = A     + (size_t)b * 589824 + (size_t)jc * 9;

    // prefetch row 0
    float2 p[12];
    {
        const float2* tp = (const float2*)thb;
        const float2* ap = (const float2*)Ab;
        p[0]=__ldg(tp); p[1]=__ldg(tp+1); p[2]=__ldg(tp+2);
        #pragma unroll
        for(int k = 0; k < 9; k++) p[3+k] = __ldg(ap + k);
    }

    float pv0e=NEG_INF, pv1e=NEG_INF, pv2e=NEG_INF;
    float pv0o=NEG_INF, pv1o=NEG_INF, pv2o=NEG_INF;
    float u0in=NEG_INF, u1in=NEG_INF, xin=NEG_INF;   // carry-in (w==0: constants)

    // prologue: head-pairs for row 0 from boundary V (NEG_INF; cell(0,0)=0)
    float bv0 = (w == 0 && lane == 0) ? 0.0f : NEG_INF;
    float Pu0e = lse2(fmaf(p[3].x, INVLN2, bv0),     fmaf(p[3].y, INVLN2, bv0));
    float Pu1e = lse2(fmaf(p[4].y, INVLN2, NEG_INF), fmaf(p[5].x, INVLN2, NEG_INF));
    float Pn0o = lse2(fmaf(p[7].y, INVLN2, NEG_INF), fmaf(p[8].x, INVLN2, NEG_INF));
    float Pn1o = lse2(fmaf(p[9].x, INVLN2, NEG_INF), fmaf(p[9].y, INVLN2, NEG_INF));
    float dlate = bv0;   // V2 at col 64w-1 of prev row (late diag term for u0e)

    for(int r = 0; r < N; r++){
        // extract row-r scalars needed this iteration (pair coefs were consumed
        // at the previous tail)
        float t0e=p[0].x, t1e=p[0].y, t2e=p[1].x*INVLN2;
        float t0o=p[1].y, t1o=p[2].x, t2o=p[2].y*INVLN2;
        float e2=p[4].x, e5=p[5].y, e6=p[6].x, e7=p[6].y, e8=p[7].x;
        float o2=p[8].y, o5=p[10].x, o6=p[10].y, o7=p[11].x, o8=p[11].y;

        // prefetch row r+1 (consumed by this iteration's tail + next top)
        if(r + 1 < N){
            const float2* tp = (const float2*)(thb + (size_t)(r+1)*768);
            const float2* ap = (const float2*)(Ab  + (size_t)(r+1)*2304);
            p[0]=__ldg(tp); p[1]=__ldg(tp+1); p[2]=__ldg(tp+2);
            #pragma unroll
            for(int k = 0; k < 9; k++) p[3+k] = __ldg(ap + k);
        }

        // heads: single lse2 fold of the precomputed pair with the late V2 term
        float u0e  = fmaf(t0e, INVLN2, lse2(Pu0e, fmaf(e2, INVLN2, dlate)));
        float u1e  = fmaf(t1e, INVLN2, lse2(Pu1e, fmaf(e5, INVLN2, pv2e)));
        float nu0o = fmaf(t0o, INVLN2, lse2(Pn0o, fmaf(o2, INVLN2, pv2e)));
        float nu1o = fmaf(t1o, INVLN2, lse2(Pn1o, fmaf(o5, INVLN2, pv2o)));

        float num0 = __shfl_up_sync(0xffffffffu, nu0o, 1);
        float num1 = __shfl_up_sync(0xffffffffu, nu1o, 1);

        // FADD prefix-sum of a (off-chain)
        float a_e = fmaf(e8, INVLN2, t2e), a_o = fmaf(o8, INVLN2, t2o);
        float Sin = a_e + a_o;
        #pragma unroll
        for(int dlt = 1; dlt < 32; dlt <<= 1){
            float v = __shfl_up_sync(0xffffffffu, Sin, dlt);
            Sin += (lane >= dlt) ? v : 0.0f;
        }
        float Sl_o = Sin, Sl_e = Sin - a_o;

        float c_o = t2o + lse2(fmaf(o6, INVLN2, u0e),  fmaf(o7, INVLN2, u1e));
        float c_e = t2e + lse2(fmaf(e6, INVLN2, num0), fmaf(e7, INVLN2, num1));
        float Te  = (lane == 0) ? M_EMPTY : c_e - Sl_e;
        float To  = c_o - Sl_o;

        float Mi = fmaxf(Te, To);
        float Qi = 1.0f + ex2f(-fabsf(Te - To));
        #pragma unroll
        for(int dlt = 1; dlt < 32; dlt <<= 1){
            float Mn = __shfl_up_sync(0xffffffffu, Mi, dlt);
            float Qn = __shfl_up_sync(0xffffffffu, Qi, dlt);
            bool take = (lane >= dlt);
            Mn = take ? Mn : M_EMPTY;
            Qn = take ? Qn : 0.0f;
            mqcomb(Mi, Qi, Mn, Qn);
        }
        float eM = __shfl_up_sync(0xffffffffu, Mi, 1);
        float eQ = __shfl_up_sync(0xffffffffu, Qi, 1);
        float WeM = (lane == 0) ? M_EMPTY : eM;
        float WeQ = (lane == 0) ? 0.0f    : eQ;
        mqcomb(WeM, WeQ, Te, 1.0f);

        // carry from warp w-1 (row r): u0,u1,x at col 64w-1
        if(w > 0){
            while(ld_acquire_s32(flag_prev) < r + 1){ }
            float4 ps = pay[w-1][r & 7];
            u0in = ps.x; u1in = ps.y; xin = ps.z;
            if(lane == 0) st_release_s32(ack_own, r + 1);
        }

        // lane-0 element + incoming x folded post-scan as one (M,Q) element
        float ce0 = t2e + lse2(fmaf(e6, INVLN2, u0in), fmaf(e7, INVLN2, u1in));
        float cb  = __shfl_sync(0xffffffffu, ce0 - a_e, 0);
        float zM  = fmaxf(xin, cb);
        float zQ  = 1.0f + ex2f(-fabsf(xin - cb));

        mqcomb(WeM, WeQ, zM, zQ);
        float x_e = Sl_e + WeM + lg2f(WeQ);
        float XoM = Mi, XoQ = Qi;
        mqcomb(XoM, XoQ, zM, zQ);
        float x_o = Sl_o + XoM + lg2f(XoQ);

        // post carry to warp w+1
        if(w < 3){
            if(lane == 31){
                while(ld_acquire_s32(ack_next) < r - 7){ }
                pay[w][r & 7] = make_float4(nu0o, nu1o, x_o, 0.0f);
                st_release_s32(flag_own, r + 1);
            }
        }

        // TAIL: head-pairs for row r+1 (p now holds row r+1). Off the x-chain.
        float d0n = (lane == 0) ? u0in : num0;   // V0 at col 64w-1, this row
        float d1n = (lane == 0) ? u1in : num1;
        Pu0e = lse2(fmaf(p[3].x, INVLN2, d0n),  fmaf(p[3].y, INVLN2, d1n));
        Pu1e = lse2(fmaf(p[4].y, INVLN2, u0e),  fmaf(p[5].x, INVLN2, u1e));
        Pn0o = lse2(fmaf(p[7].y, INVLN2, u0e),  fmaf(p[8].x, INVLN2, u1e));
        Pn1o = lse2(fmaf(p[9].x, INVLN2, nu0o), fmaf(p[9].y, INVLN2, nu1o));
        float sxo = __shfl_up_sync(0xffffffffu, x_o, 1);
        dlate = (lane == 0) ? xin : sxo;

        pv0e = u0e;  pv1e = u1e;  pv2e = x_e;
        pv0o = nu0o; pv1o = nu1o; pv2o = x_o;
    }

    if(w == 3 && lane == 31) out[b] = LN2 * lse3(pv0o, pv1o, pv2o);
}

extern "C" void kernel_launch(void* const* d_in, const int* in_sizes, int n_in,
                              void* d_out, int out_size) {
    const float* theta = (const float*)d_in[0];
    const float* A     = (const float*)d_in[1];
    // d_in[2] = pos: fixed [(-1,-1),(-1,0),(0,-1)] -> (diag, up, left), hard-coded.
    float* out = (float*)d_out;
    int B = out_size;   // 128 batches, one CTA each
    forward_decoder_kernel<<<B, 128>>>(theta, A, out);
}